// round 13
// baseline (speedup 1.0000x reference)
#include <cuda_runtime.h>
#include <cuda_fp16.h>
#include <cstdint>

#define NNODES 50000
#define NEDGES 600000
#define NB     ((NNODES + 255) / 256)   /* 196 scan blocks */
#define SR     68    /* A-tile smem row stride (words): conflict-free ldmatrix */
#define WR     36    /* W2 smem row stride (words): conflict-free ldmatrix.trans */
#define GEMM128_SMEM ((128 * SR + 128 * SR) * 4)   /* 69632 bytes */
#define FUSED_SMEM   ((128 * SR + 128 * WR) * 4)   /* 53248 bytes */

// ---------------- scratch (static device globals; no allocation) -------------
__device__ __align__(16) uint32_t g_h1h [NNODES * 64];  // x@W1, half2 packed
__device__ __align__(16) uint32_t g_h2h [NNODES * 20];  // layer2 pre-agg, half2
__device__ float g_dinv[NNODES];
__device__ int   g_degi[NNODES];           // zero-init; re-zeroed by scan
__device__ int   g_rowstart[NNODES + 1];
__device__ int   g_cursor[NNODES];
__device__ int   g_csr_src[NEDGES];
// decoupled-lookback state (zero-init; reset by csrfill each replay)
__device__ int                g_ticket;
__device__ unsigned long long g_packed[NB];  // (flag<<32)|value; 1=agg, 2=prefix

// ---------------- helpers ------------------------------------------------------
__device__ __forceinline__ uint32_t pkh2(float a, float b) {
    __half2 h = __floats2half2_rn(a, b);
    return *reinterpret_cast<uint32_t*>(&h);
}
__device__ __forceinline__ float2 h2f2(uint32_t u) {
    __half2 h = *reinterpret_cast<__half2*>(&u);
    return __half22float2(h);
}
__device__ __forceinline__ void mma_f16(
    float& d0, float& d1, float& d2, float& d3,
    uint32_t a0, uint32_t a1, uint32_t a2, uint32_t a3,
    uint32_t b0, uint32_t b1)
{
    asm volatile(
        "mma.sync.aligned.m16n8k16.row.col.f32.f16.f16.f32 "
        "{%0,%1,%2,%3}, {%4,%5,%6,%7}, {%8,%9}, {%0,%1,%2,%3};"
        : "+f"(d0), "+f"(d1), "+f"(d2), "+f"(d3)
        : "r"(a0), "r"(a1), "r"(a2), "r"(a3), "r"(b0), "r"(b1));
}
__device__ __forceinline__ void ldsm_x4(
    uint32_t& r0, uint32_t& r1, uint32_t& r2, uint32_t& r3, uint32_t addr)
{
    asm volatile("ldmatrix.sync.aligned.m8n8.x4.shared.b16 {%0,%1,%2,%3}, [%4];"
        : "=r"(r0), "=r"(r1), "=r"(r2), "=r"(r3) : "r"(addr));
}
__device__ __forceinline__ void ldsm_x4t(
    uint32_t& r0, uint32_t& r1, uint32_t& r2, uint32_t& r3, uint32_t addr)
{
    asm volatile("ldmatrix.sync.aligned.m8n8.x4.trans.shared.b16 {%0,%1,%2,%3}, [%4];"
        : "=r"(r0), "=r"(r1), "=r"(r2), "=r"(r3) : "r"(addr));
}

// ---------------- degree (4 edges per thread) ---------------------------------
__global__ void degree_kernel(const int* __restrict__ ei) {
    int e4 = blockIdx.x * blockDim.x + threadIdx.x;
    if (e4 * 4 >= NEDGES) return;
    int4 d = *(const int4*)&ei[NEDGES + e4 * 4];
    atomicAdd(&g_degi[d.x], 1);
    atomicAdd(&g_degi[d.y], 1);
    atomicAdd(&g_degi[d.z], 1);
    atomicAdd(&g_degi[d.w], 1);
}

// ---------------- fused scan: dinv + rowstart + cursor (warp lookback) --------
__global__ __launch_bounds__(256) void scan_fused_kernel() {
    __shared__ int s[256];
    __shared__ int sh_bid;
    __shared__ int sh_prefix;

    int t = threadIdx.x;
    if (t == 0) sh_bid = atomicAdd(&g_ticket, 1);
    __syncthreads();
    int b   = sh_bid;
    int gid = b * 256 + t;

    int d = (gid < NNODES) ? g_degi[gid] : 0;
    if (gid < NNODES) {
        g_dinv[gid] = rsqrtf((float)d + 1.0f);
        g_degi[gid] = 0;                       // reset for next replay
    }
    s[t] = d;
    __syncthreads();
#pragma unroll
    for (int off = 1; off < 256; off <<= 1) {
        int v = (t >= off) ? s[t - off] : 0;
        __syncthreads();
        if (t >= off) s[t] += v;
        __syncthreads();
    }
    int incl = s[t];
    int aggregate = s[255];

    if (t == 0)
        atomicExch(&g_packed[b], (1ULL << 32) | (unsigned)aggregate);

    if (t < 32) {   // warp 0: parallel lookback
        int run = 0;
        int p = b - 1;
        while (p >= 0) {
            int idx = p - t;
            unsigned long long v = 0ULL;
            if (idx >= 0) {
                do { v = *((volatile unsigned long long*)&g_packed[idx]); }
                while ((v >> 32) == 0ULL);
            }
            unsigned flag = (unsigned)(v >> 32);
            unsigned val  = (unsigned)v;
            unsigned ball = __ballot_sync(0xffffffffu, flag == 2u);
            int lp = ball ? (__ffs(ball) - 1) : 32;
            if (t > lp) val = 0;
#pragma unroll
            for (int o = 16; o; o >>= 1)
                val += __shfl_xor_sync(0xffffffffu, val, o);
            run += (int)val;
            if (ball) break;
            p -= 32;
        }
        if (t == 0) {
            atomicExch(&g_packed[b], (2ULL << 32) | (unsigned)(run + aggregate));
            sh_prefix = run;
        }
    }
    __syncthreads();

    if (gid < NNODES) {
        int r = sh_prefix + incl - d;
        g_rowstart[gid] = r;
        g_cursor[gid]   = r;
    }
    if (gid == 0) g_rowstart[NNODES] = NEDGES;
}

// ---------------- CSR fill: src only (nrm computed in gathers) ----------------
__global__ void csrfill_kernel(const int* __restrict__ ei) {
    int e = blockIdx.x * blockDim.x + threadIdx.x;
    if (e < NB)  g_packed[e] = 0ULL;           // reset scan state for next replay
    if (e == NB) g_ticket = 0;
    if (e >= NEDGES) return;
    int s = ei[e];
    int d = ei[NEDGES + e];
    int pos = atomicAdd(&g_cursor[d], 1);
    g_csr_src[pos] = s;
}

// ---------------- single-shot fp16 GEMM (ldmatrix): [M,128] @ [128,128] -------
__global__ __launch_bounds__(256) void gemm128_f16_kernel(
    const float* __restrict__ A, const float* __restrict__ W,
    uint32_t* __restrict__ C, int M)
{
    extern __shared__ uint32_t sm[];
    uint32_t* xs = sm;             // [row 0..127][k2 0..63]  stride SR words
    uint32_t* wh = sm + 128 * SR;  // [k  0..127][n half2 0..63] stride SR words

    int tid  = threadIdx.x;
    int w    = tid >> 5;
    int lane = tid & 31;
    int g    = lane >> 2;
    int t4   = lane & 3;
    int r0   = blockIdx.x * 128;

#pragma unroll
    for (int L = tid; L < 4096; L += 256) {
        int r  = L >> 5;
        int kg = L & 31;
        int row = r0 + r;
        float4 v = make_float4(0.f, 0.f, 0.f, 0.f);
        if (row < M)
            v = *(const float4*)&A[(size_t)row * 128 + kg * 4];
        *(uint2*)&xs[r * SR + kg * 2] = make_uint2(pkh2(v.x, v.y), pkh2(v.z, v.w));
    }
#pragma unroll
    for (int L = tid; L < 4096; L += 256) {
        int k  = L >> 5;
        int ng = L & 31;
        float4 v = *(const float4*)&W[(size_t)k * 128 + ng * 4];
        *(uint2*)&wh[k * SR + ng * 2] = make_uint2(pkh2(v.x, v.y), pkh2(v.z, v.w));
    }
    __syncthreads();

    float acc[16][4];
#pragma unroll
    for (int j = 0; j < 16; j++)
#pragma unroll
        for (int i = 0; i < 4; i++) acc[j][i] = 0.f;

    uint32_t sbase = (uint32_t)__cvta_generic_to_shared(sm);
    uint32_t a_addr = sbase + (((w * 16 + (lane & 15)) * SR + ((lane >> 4) << 2)) << 2);
    uint32_t b_addr = sbase + ((128 * SR + (lane & 15) * SR + ((lane >> 4) << 2)) << 2);

#pragma unroll
    for (int m = 0; m < 8; m++) {
        uint32_t a0, a1, a2, a3;
        ldsm_x4(a0, a1, a2, a3, a_addr + m * 32);
        uint32_t bb = b_addr + m * 16 * SR * 4;
#pragma unroll
        for (int j = 0; j < 16; j += 2) {
            uint32_t b0, b1, b2, b3;
            ldsm_x4t(b0, b1, b2, b3, bb + j * 16);
            mma_f16(acc[j][0],   acc[j][1],   acc[j][2],   acc[j][3],
                    a0, a1, a2, a3, b0, b1);
            mma_f16(acc[j+1][0], acc[j+1][1], acc[j+1][2], acc[j+1][3],
                    a0, a1, a2, a3, b2, b3);
        }
    }

    int rowA = r0 + w * 16 + g;
#pragma unroll
    for (int j = 0; j < 16; j++) {
        if (rowA < M)
            C[(size_t)rowA * 64 + j * 4 + t4] = pkh2(acc[j][0], acc[j][1]);
        if (rowA + 8 < M)
            C[(size_t)(rowA + 8) * 64 + j * 4 + t4] = pkh2(acc[j][2], acc[j][3]);
    }
}

// ---------------- FUSED: gather layer-1 (relu) into smem + GEMM [128x40] ------
// Each block owns 128 nodes: 8 warps gather 16 nodes each (CSR, inline nrm),
// write h1b rows straight into the MMA A-tile in smem, one sync, then MMA vs W2.
__global__ __launch_bounds__(256) void gather_gemm40_kernel(
    const float* __restrict__ b1, const float* __restrict__ W2,
    uint32_t* __restrict__ C)
{
    extern __shared__ uint32_t sm[];
    uint32_t* xs = sm;             // [row 0..127][k2 0..63] stride SR words
    uint32_t* wh = sm + 128 * SR;  // [k 0..127][word 0..23] stride WR words

    int tid  = threadIdx.x;
    int w    = tid >> 5;
    int lane = tid & 31;
    int g    = lane >> 2;
    int t4   = lane & 3;
    int r0   = blockIdx.x * 128;

    // W2 tile fill + zero pad (no sync needed before the MMA-phase sync)
#pragma unroll
    for (int L = tid; L < 512; L += 256) {
        int k = L >> 2;
        wh[k * WR + 20 + (L & 3)] = 0u;
    }
#pragma unroll
    for (int L = tid; L < 1280; L += 256) {
        int k  = L / 10;
        int ng = L % 10;
        float4 v = *(const float4*)&W2[(size_t)k * 40 + ng * 4];
        *(uint2*)&wh[k * WR + ng * 2] = make_uint2(pkh2(v.x, v.y), pkh2(v.z, v.w));
    }

    // ---- gather phase: warp w handles nodes r0 + w*16 .. +15 ----
    const uint2* __restrict__ h = (const uint2*)g_h1h;   // lane = channels 4l..4l+3
    float4 bv = ((const float4*)b1)[lane];

    for (int i = 0; i < 16; i++) {
        int node = r0 + w * 16 + i;
        if (node >= NNODES) break;
        int start = g_rowstart[node];
        int end   = g_rowstart[node + 1];
        float ddst = g_dinv[node];

        float a0 = 0.f, a1 = 0.f, a2 = 0.f, a3 = 0.f;
        int j = start;
        for (; j + 3 < end; j += 4) {
            int s0 = __ldg(&g_csr_src[j]);
            int s1 = __ldg(&g_csr_src[j + 1]);
            int s2 = __ldg(&g_csr_src[j + 2]);
            int s3 = __ldg(&g_csr_src[j + 3]);
            float n0 = __ldg(&g_dinv[s0]) * ddst;
            float n1 = __ldg(&g_dinv[s1]) * ddst;
            float n2 = __ldg(&g_dinv[s2]) * ddst;
            float n3 = __ldg(&g_dinv[s3]) * ddst;
            uint2 u0 = h[(size_t)s0 * 32 + lane];
            uint2 u1 = h[(size_t)s1 * 32 + lane];
            uint2 u2 = h[(size_t)s2 * 32 + lane];
            uint2 u3 = h[(size_t)s3 * 32 + lane];
            float2 p, q;
            p = h2f2(u0.x); q = h2f2(u0.y);
            a0 = fmaf(n0, p.x, a0); a1 = fmaf(n0, p.y, a1);
            a2 = fmaf(n0, q.x, a2); a3 = fmaf(n0, q.y, a3);
            p = h2f2(u1.x); q = h2f2(u1.y);
            a0 = fmaf(n1, p.x, a0); a1 = fmaf(n1, p.y, a1);
            a2 = fmaf(n1, q.x, a2); a3 = fmaf(n1, q.y, a3);
            p = h2f2(u2.x); q = h2f2(u2.y);
            a0 = fmaf(n2, p.x, a0); a1 = fmaf(n2, p.y, a1);
            a2 = fmaf(n2, q.x, a2); a3 = fmaf(n2, q.y, a3);
            p = h2f2(u3.x); q = h2f2(u3.y);
            a0 = fmaf(n3, p.x, a0); a1 = fmaf(n3, p.y, a1);
            a2 = fmaf(n3, q.x, a2); a3 = fmaf(n3, q.y, a3);
        }
        for (; j < end; ++j) {
            int s0 = __ldg(&g_csr_src[j]);
            float n0 = __ldg(&g_dinv[s0]) * ddst;
            uint2 u0 = h[(size_t)s0 * 32 + lane];
            float2 p = h2f2(u0.x), q = h2f2(u0.y);
            a0 = fmaf(n0, p.x, a0); a1 = fmaf(n0, p.y, a1);
            a2 = fmaf(n0, q.x, a2); a3 = fmaf(n0, q.y, a3);
        }

        // epilogue: self loop + bias + relu -> pack -> smem A-tile row
        float d2 = ddst * ddst;
        uint2 us = h[(size_t)node * 32 + lane];
        float2 p = h2f2(us.x), q = h2f2(us.y);
        float e0 = fmaxf(fmaf(p.x, d2, a0) + bv.x, 0.f);
        float e1 = fmaxf(fmaf(p.y, d2, a1) + bv.y, 0.f);
        float e2 = fmaxf(fmaf(q.x, d2, a2) + bv.z, 0.f);
        float e3 = fmaxf(fmaf(q.y, d2, a3) + bv.w, 0.f);
        *(uint2*)&xs[(w * 16 + i) * SR + lane * 2] =
            make_uint2(pkh2(e0, e1), pkh2(e2, e3));
    }
    __syncthreads();

    // ---- MMA phase: [128,128]h1b @ [128,40]W2 -> h2 ----
    float acc[6][4];
#pragma unroll
    for (int j = 0; j < 6; j++)
#pragma unroll
        for (int i = 0; i < 4; i++) acc[j][i] = 0.f;

    uint32_t sbase = (uint32_t)__cvta_generic_to_shared(sm);
    uint32_t a_addr = sbase + (((w * 16 + (lane & 15)) * SR + ((lane >> 4) << 2)) << 2);
    uint32_t b_addr = sbase + ((128 * SR + (lane & 15) * WR + ((lane >> 4) << 2)) << 2);

#pragma unroll
    for (int m = 0; m < 8; m++) {
        uint32_t a0, a1, a2, a3;
        ldsm_x4(a0, a1, a2, a3, a_addr + m * 32);
        uint32_t bb = b_addr + m * 16 * WR * 4;
#pragma unroll
        for (int j = 0; j < 6; j += 2) {
            uint32_t b0, b1, b2, b3;
            ldsm_x4t(b0, b1, b2, b3, bb + j * 16);
            mma_f16(acc[j][0],   acc[j][1],   acc[j][2],   acc[j][3],
                    a0, a1, a2, a3, b0, b1);
            mma_f16(acc[j+1][0], acc[j+1][1], acc[j+1][2], acc[j+1][3],
                    a0, a1, a2, a3, b2, b3);
        }
    }

    int rowA = r0 + w * 16 + g;
#pragma unroll
    for (int j = 0; j < 5; j++) {
        if (rowA < NNODES)
            C[(size_t)rowA * 20 + j * 4 + t4] = pkh2(acc[j][0], acc[j][1]);
        if (rowA + 8 < NNODES)
            C[(size_t)(rowA + 8) * 20 + j * 4 + t4] = pkh2(acc[j][2], acc[j][3]);
    }
}

// ---------------- gather layer 2 (C=40): two nodes per warp, inline nrm -------
__global__ __launch_bounds__(256) void gather40_kernel(const float* __restrict__ b2,
                                                       float* __restrict__ out) {
    int w = (blockIdx.x * blockDim.x + threadIdx.x) >> 5;
    int lane = threadIdx.x & 31;
    int node = w * 2 + (lane >> 4);
    if (node >= NNODES) return;
    int sub = lane & 15;
    bool active = sub < 10;

    int start = g_rowstart[node];
    int end   = g_rowstart[node + 1];
    float ddst = g_dinv[node];

    const uint2* __restrict__ h = (const uint2*)g_h2h;
    float4 acc = make_float4(0.f, 0.f, 0.f, 0.f);

    int j = start;
    for (; j + 1 < end; j += 2) {
        int s0 = __ldg(&g_csr_src[j]);
        int s1 = __ldg(&g_csr_src[j + 1]);
        float n0 = __ldg(&g_dinv[s0]) * ddst;
        float n1 = __ldg(&g_dinv[s1]) * ddst;
        if (active) {
            uint2 u0 = h[(size_t)s0 * 10 + sub];
            uint2 u1 = h[(size_t)s1 * 10 + sub];
            float2 a, b;
            a = h2f2(u0.x); b = h2f2(u0.y);
            acc.x = fmaf(n0, a.x, acc.x); acc.y = fmaf(n0, a.y, acc.y);
            acc.z = fmaf(n0, b.x, acc.z); acc.w = fmaf(n0, b.y, acc.w);
            a = h2f2(u1.x); b = h2f2(u1.y);
            acc.x = fmaf(n1, a.x, acc.x); acc.y = fmaf(n1, a.y, acc.y);
            acc.z = fmaf(n1, b.x, acc.z); acc.w = fmaf(n1, b.y, acc.w);
        }
    }
    if (j < end) {
        int s0 = __ldg(&g_csr_src[j]);
        float n0 = __ldg(&g_dinv[s0]) * ddst;
        if (active) {
            uint2 u0 = h[(size_t)s0 * 10 + sub];
            float2 a = h2f2(u0.x), b = h2f2(u0.y);
            acc.x = fmaf(n0, a.x, acc.x); acc.y = fmaf(n0, a.y, acc.y);
            acc.z = fmaf(n0, b.x, acc.z); acc.w = fmaf(n0, b.y, acc.w);
        }
    }

    if (active) {
        float d2 = ddst * ddst;
        uint2 us = h[(size_t)node * 10 + sub];
        float2 ha = h2f2(us.x), hb = h2f2(us.y);
        float4 bb = ((const float4*)b2)[sub];
        float4 r;
        r.x = fmaf(ha.x, d2, acc.x) + bb.x;
        r.y = fmaf(ha.y, d2, acc.y) + bb.y;
        r.z = fmaf(hb.x, d2, acc.z) + bb.z;
        r.w = fmaf(hb.y, d2, acc.w) + bb.w;
        *(float4*)&out[(size_t)node * 40 + sub * 4] = r;
    }
}

// -----------------------------------------------------------------------------
extern "C" void kernel_launch(void* const* d_in, const int* in_sizes, int n_in,
                              void* d_out, int out_size) {
    const float* x   = (const float*)d_in[0];
    const int*   ei  = (const int*)  d_in[1];
    const float* W1  = (const float*)d_in[2];
    const float* b1  = (const float*)d_in[3];
    const float* W2  = (const float*)d_in[4];
    const float* b2  = (const float*)d_in[5];
    float* out = (float*)d_out;

    static bool s_init = false;
    static cudaStream_t s2;
    static cudaEvent_t evA, evB;
    if (!s_init) {   // host-side setup on first (uncaptured) call only
        cudaFuncSetAttribute(gemm128_f16_kernel,
                             cudaFuncAttributeMaxDynamicSharedMemorySize, GEMM128_SMEM);
        cudaFuncSetAttribute(gather_gemm40_kernel,
                             cudaFuncAttributeMaxDynamicSharedMemorySize, FUSED_SMEM);
        cudaStreamCreateWithFlags(&s2, cudaStreamNonBlocking);
        cudaEventCreateWithFlags(&evA, cudaEventDisableTiming);
        cudaEventCreateWithFlags(&evB, cudaEventDisableTiming);
        s_init = true;
    }

    uint32_t* h1_p;  cudaGetSymbolAddress((void**)&h1_p,  g_h1h);
    uint32_t* h2_p;  cudaGetSymbolAddress((void**)&h2_p,  g_h2h);

    // ---- fork: CSR build on s2, concurrent with gemm128 on main stream ----
    cudaEventRecord(evA, 0);
    cudaStreamWaitEvent(s2, evA, 0);
    degree_kernel<<<(NEDGES / 4 + 255) / 256, 256, 0, s2>>>(ei);
    scan_fused_kernel<<<NB, 256, 0, s2>>>();
    csrfill_kernel<<<(NEDGES + 255) / 256, 256, 0, s2>>>(ei);
    cudaEventRecord(evB, s2);

    gemm128_f16_kernel<<<(NNODES + 127) / 128, 256, GEMM128_SMEM>>>(x, W1, h1_p, NNODES);

    // ---- join, then the fused tail ----
    cudaStreamWaitEvent(0, evB, 0);
    gather_gemm40_kernel<<<(NNODES + 127) / 128, 256, FUSED_SMEM>>>(b1, W2, h2_p);
    gather40_kernel<<<((NNODES + 1) / 2 * 32 + 255) / 256, 256>>>(b2, out);
}

// round 14
// speedup vs baseline: 1.1547x; 1.1547x over previous
#include <cuda_runtime.h>
#include <cuda_fp16.h>
#include <cstdint>

#define NNODES 50000
#define NEDGES 600000
#define NB     ((NNODES + 255) / 256)   /* 196 scan blocks */
#define SR     68    /* smem row stride in words: row starts quad-aligned banks */
#define WR     36    /* W2 smem row stride (words): conflict-free ldmatrix.trans */
#define GEMM128_SMEM ((128 * SR + 128 * SR) * 4)   /* 69632 bytes */
#define GEMM40_SMEM  ((128 * SR + 128 * WR) * 4)   /* 53248 bytes */

// ---------------- scratch (static device globals; no allocation) -------------
__device__ __align__(16) uint32_t g_h1h [NNODES * 64];  // x@W1, half2 packed
__device__ __align__(16) uint32_t g_h1bh[NNODES * 64];  // relu layer-1 out, half2
__device__ __align__(16) uint32_t g_h2h [NNODES * 20];  // h1b@W2, half2
__device__ float g_dinv[NNODES];
__device__ int   g_degi[NNODES];           // zero-init; re-zeroed by scan
__device__ int   g_rowstart[NNODES + 1];
__device__ int   g_cursor[NNODES];
__device__ int   g_csr_src[NEDGES];
__device__ float g_csr_nrm[NEDGES];
// decoupled-lookback state (zero-init; reset by csrfill each replay)
__device__ int                g_ticket;
__device__ unsigned long long g_packed[NB];  // (flag<<32)|value; 1=agg, 2=prefix

// ---------------- helpers ------------------------------------------------------
__device__ __forceinline__ uint32_t pkh2(float a, float b) {
    __half2 h = __floats2half2_rn(a, b);
    return *reinterpret_cast<uint32_t*>(&h);
}
__device__ __forceinline__ float2 h2f2(uint32_t u) {
    __half2 h = *reinterpret_cast<__half2*>(&u);
    return __half22float2(h);
}
__device__ __forceinline__ void mma_f16(
    float& d0, float& d1, float& d2, float& d3,
    uint32_t a0, uint32_t a1, uint32_t a2, uint32_t a3,
    uint32_t b0, uint32_t b1)
{
    asm volatile(
        "mma.sync.aligned.m16n8k16.row.col.f32.f16.f16.f32 "
        "{%0,%1,%2,%3}, {%4,%5,%6,%7}, {%8,%9}, {%0,%1,%2,%3};"
        : "+f"(d0), "+f"(d1), "+f"(d2), "+f"(d3)
        : "r"(a0), "r"(a1), "r"(a2), "r"(a3), "r"(b0), "r"(b1));
}
__device__ __forceinline__ void ldsm_x4(
    uint32_t& r0, uint32_t& r1, uint32_t& r2, uint32_t& r3, uint32_t addr)
{
    asm volatile("ldmatrix.sync.aligned.m8n8.x4.shared.b16 {%0,%1,%2,%3}, [%4];"
        : "=r"(r0), "=r"(r1), "=r"(r2), "=r"(r3) : "r"(addr));
}
__device__ __forceinline__ void ldsm_x4t(
    uint32_t& r0, uint32_t& r1, uint32_t& r2, uint32_t& r3, uint32_t addr)
{
    asm volatile("ldmatrix.sync.aligned.m8n8.x4.trans.shared.b16 {%0,%1,%2,%3}, [%4];"
        : "=r"(r0), "=r"(r1), "=r"(r2), "=r"(r3) : "r"(addr));
}

// ---------------- degree (4 edges per thread) ---------------------------------
__global__ void degree_kernel(const int* __restrict__ ei) {
    int e4 = blockIdx.x * blockDim.x + threadIdx.x;
    if (e4 * 4 >= NEDGES) return;
    int4 d = *(const int4*)&ei[NEDGES + e4 * 4];
    atomicAdd(&g_degi[d.x], 1);
    atomicAdd(&g_degi[d.y], 1);
    atomicAdd(&g_degi[d.z], 1);
    atomicAdd(&g_degi[d.w], 1);
}

// ---------------- fused scan: dinv + rowstart + cursor (warp lookback) --------
__global__ __launch_bounds__(256) void scan_fused_kernel() {
    __shared__ int s[256];
    __shared__ int sh_bid;
    __shared__ int sh_prefix;

    int t = threadIdx.x;
    if (t == 0) sh_bid = atomicAdd(&g_ticket, 1);
    __syncthreads();
    int b   = sh_bid;
    int gid = b * 256 + t;

    int d = (gid < NNODES) ? g_degi[gid] : 0;
    if (gid < NNODES) {
        g_dinv[gid] = rsqrtf((float)d + 1.0f);
        g_degi[gid] = 0;                       // reset for next replay
    }
    s[t] = d;
    __syncthreads();
#pragma unroll
    for (int off = 1; off < 256; off <<= 1) {
        int v = (t >= off) ? s[t - off] : 0;
        __syncthreads();
        if (t >= off) s[t] += v;
        __syncthreads();
    }
    int incl = s[t];
    int aggregate = s[255];

    if (t == 0)
        atomicExch(&g_packed[b], (1ULL << 32) | (unsigned)aggregate);

    if (t < 32) {   // warp 0: parallel lookback
        int run = 0;
        int p = b - 1;
        while (p >= 0) {
            int idx = p - t;
            unsigned long long v = 0ULL;
            if (idx >= 0) {
                do { v = *((volatile unsigned long long*)&g_packed[idx]); }
                while ((v >> 32) == 0ULL);
            }
            unsigned flag = (unsigned)(v >> 32);
            unsigned val  = (unsigned)v;
            unsigned ball = __ballot_sync(0xffffffffu, flag == 2u);
            int lp = ball ? (__ffs(ball) - 1) : 32;
            if (t > lp) val = 0;
#pragma unroll
            for (int o = 16; o; o >>= 1)
                val += __shfl_xor_sync(0xffffffffu, val, o);
            run += (int)val;
            if (ball) break;
            p -= 32;
        }
        if (t == 0) {
            atomicExch(&g_packed[b], (2ULL << 32) | (unsigned)(run + aggregate));
            sh_prefix = run;
        }
    }
    __syncthreads();

    if (gid < NNODES) {
        int r = sh_prefix + incl - d;
        g_rowstart[gid] = r;
        g_cursor[gid]   = r;
    }
    if (gid == 0) g_rowstart[NNODES] = NEDGES;
}

// ---------------- CSR fill (also resets scan state for next replay) ----------
__global__ void csrfill_kernel(const int* __restrict__ ei) {
    int e = blockIdx.x * blockDim.x + threadIdx.x;
    if (e < NB)  g_packed[e] = 0ULL;
    if (e == NB) g_ticket = 0;
    if (e >= NEDGES) return;
    int s = ei[e];
    int d = ei[NEDGES + e];
    int pos = atomicAdd(&g_cursor[d], 1);
    g_csr_src[pos] = s;
    g_csr_nrm[pos] = g_dinv[s] * g_dinv[d];
}

// ---------------- single-shot fp16 GEMM (ldmatrix): [M,128] @ [128,128] -------
__global__ __launch_bounds__(256) void gemm128_f16_kernel(
    const float* __restrict__ A, const float* __restrict__ W,
    uint32_t* __restrict__ C, int M)
{
    extern __shared__ uint32_t sm[];
    uint32_t* xs = sm;             // [row 0..127][k2 0..63]  stride SR words
    uint32_t* wh = sm + 128 * SR;  // [k  0..127][n half2 0..63] stride SR words

    int tid  = threadIdx.x;
    int w    = tid >> 5;
    int lane = tid & 31;
    int g    = lane >> 2;
    int t4   = lane & 3;
    int r0   = blockIdx.x * 128;

#pragma unroll
    for (int L = tid; L < 4096; L += 256) {
        int r  = L >> 5;
        int kg = L & 31;
        int row = r0 + r;
        float4 v = make_float4(0.f, 0.f, 0.f, 0.f);
        if (row < M)
            v = *(const float4*)&A[(size_t)row * 128 + kg * 4];
        *(uint2*)&xs[r * SR + kg * 2] = make_uint2(pkh2(v.x, v.y), pkh2(v.z, v.w));
    }
#pragma unroll
    for (int L = tid; L < 4096; L += 256) {
        int k  = L >> 5;
        int ng = L & 31;
        float4 v = *(const float4*)&W[(size_t)k * 128 + ng * 4];
        *(uint2*)&wh[k * SR + ng * 2] = make_uint2(pkh2(v.x, v.y), pkh2(v.z, v.w));
    }
    __syncthreads();

    float acc[16][4];
#pragma unroll
    for (int j = 0; j < 16; j++)
#pragma unroll
        for (int i = 0; i < 4; i++) acc[j][i] = 0.f;

    uint32_t sbase = (uint32_t)__cvta_generic_to_shared(sm);
    uint32_t a_addr = sbase + (((w * 16 + (lane & 15)) * SR + ((lane >> 4) << 2)) << 2);
    uint32_t b_addr = sbase + ((128 * SR + (lane & 15) * SR + ((lane >> 4) << 2)) << 2);

#pragma unroll
    for (int m = 0; m < 8; m++) {
        uint32_t a0, a1, a2, a3;
        ldsm_x4(a0, a1, a2, a3, a_addr + m * 32);
        uint32_t bb = b_addr + m * 16 * SR * 4;
#pragma unroll
        for (int j = 0; j < 16; j += 2) {
            uint32_t b0, b1, b2, b3;
            ldsm_x4t(b0, b1, b2, b3, bb + j * 16);
            mma_f16(acc[j][0],   acc[j][1],   acc[j][2],   acc[j][3],
                    a0, a1, a2, a3, b0, b1);
            mma_f16(acc[j+1][0], acc[j+1][1], acc[j+1][2], acc[j+1][3],
                    a0, a1, a2, a3, b2, b3);
        }
    }

    int rowA = r0 + w * 16 + g;
#pragma unroll
    for (int j = 0; j < 16; j++) {
        if (rowA < M)
            C[(size_t)rowA * 64 + j * 4 + t4] = pkh2(acc[j][0], acc[j][1]);
        if (rowA + 8 < M)
            C[(size_t)(rowA + 8) * 64 + j * 4 + t4] = pkh2(acc[j][2], acc[j][3]);
    }
}

// ---------------- single-shot fp16 GEMM (ldmatrix): [M,128]half @ [128,40] ----
// W2 tile stride WR=36 words -> 53 KB smem -> 4 CTAs/SM.
__global__ __launch_bounds__(256) void gemm40_f16_kernel(
    const uint32_t* __restrict__ Ah, const float* __restrict__ W,
    uint32_t* __restrict__ C, int M)
{
    extern __shared__ uint32_t sm[];
    uint32_t* xs = sm;             // [row][k2] stride SR
    uint32_t* wh = sm + 128 * SR;  // [k][n half2 < 24] stride WR

    int tid  = threadIdx.x;
    int w    = tid >> 5;
    int lane = tid & 31;
    int g    = lane >> 2;
    int t4   = lane & 3;
    int r0   = blockIdx.x * 128;

#pragma unroll
    for (int L = tid; L < 2048; L += 256) {
        int r  = L >> 4;
        int kq = L & 15;
        int row = r0 + r;
        uint4 v = make_uint4(0u, 0u, 0u, 0u);
        if (row < M)
            v = *(const uint4*)&Ah[(size_t)row * 64 + kq * 4];
        *(uint4*)&xs[r * SR + kq * 4] = v;
    }
    // zero pad words (cols 40..47 = words 20..23)
#pragma unroll
    for (int L = tid; L < 512; L += 256) {
        int k = L >> 2;
        wh[k * WR + 20 + (L & 3)] = 0u;
    }
    // W2: plain [k][n<40] halves
#pragma unroll
    for (int L = tid; L < 1280; L += 256) {
        int k  = L / 10;
        int ng = L % 10;
        float4 v = *(const float4*)&W[(size_t)k * 40 + ng * 4];
        *(uint2*)&wh[k * WR + ng * 2] = make_uint2(pkh2(v.x, v.y), pkh2(v.z, v.w));
    }
    __syncthreads();

    float acc[6][4];
#pragma unroll
    for (int j = 0; j < 6; j++)
#pragma unroll
        for (int i = 0; i < 4; i++) acc[j][i] = 0.f;

    uint32_t sbase = (uint32_t)__cvta_generic_to_shared(sm);
    uint32_t a_addr = sbase + (((w * 16 + (lane & 15)) * SR + ((lane >> 4) << 2)) << 2);
    uint32_t b_addr = sbase + ((128 * SR + (lane & 15) * WR + ((lane >> 4) << 2)) << 2);

#pragma unroll
    for (int m = 0; m < 8; m++) {
        uint32_t a0, a1, a2, a3;
        ldsm_x4(a0, a1, a2, a3, a_addr + m * 32);
        uint32_t bb = b_addr + m * 16 * WR * 4;
#pragma unroll
        for (int j = 0; j < 6; j += 2) {
            uint32_t b0, b1, b2, b3;
            ldsm_x4t(b0, b1, b2, b3, bb + j * 16);
            mma_f16(acc[j][0],   acc[j][1],   acc[j][2],   acc[j][3],
                    a0, a1, a2, a3, b0, b1);
            mma_f16(acc[j+1][0], acc[j+1][1], acc[j+1][2], acc[j+1][3],
                    a0, a1, a2, a3, b2, b3);
        }
    }

    int rowA = r0 + w * 16 + g;
#pragma unroll
    for (int j = 0; j < 5; j++) {
        if (rowA < M)
            C[(size_t)rowA * 20 + j * 4 + t4] = pkh2(acc[j][0], acc[j][1]);
        if (rowA + 8 < M)
            C[(size_t)(rowA + 8) * 20 + j * 4 + t4] = pkh2(acc[j][2], acc[j][3]);
    }
}

// ---------------- gather layer 1 (C=128, fp16): warp per node -----------------
__global__ __launch_bounds__(256) void gather128_kernel(const float* __restrict__ b1) {
    int w = (blockIdx.x * blockDim.x + threadIdx.x) >> 5;
    if (w >= NNODES) return;
    int lane = threadIdx.x & 31;

    int start = g_rowstart[w];
    int end   = g_rowstart[w + 1];

    const uint2* __restrict__ h = (const uint2*)g_h1h;
    float4 acc = make_float4(0.f, 0.f, 0.f, 0.f);

    int j = start;
    for (; j + 3 < end; j += 4) {
        int   s0 = __ldg(&g_csr_src[j]);
        int   s1 = __ldg(&g_csr_src[j + 1]);
        int   s2 = __ldg(&g_csr_src[j + 2]);
        int   s3 = __ldg(&g_csr_src[j + 3]);
        float n0 = __ldg(&g_csr_nrm[j]);
        float n1 = __ldg(&g_csr_nrm[j + 1]);
        float n2 = __ldg(&g_csr_nrm[j + 2]);
        float n3 = __ldg(&g_csr_nrm[j + 3]);
        uint2 u0 = h[(size_t)s0 * 32 + lane];
        uint2 u1 = h[(size_t)s1 * 32 + lane];
        uint2 u2 = h[(size_t)s2 * 32 + lane];
        uint2 u3 = h[(size_t)s3 * 32 + lane];
        float2 a, b;
        a = h2f2(u0.x); b = h2f2(u0.y);
        acc.x = fmaf(n0, a.x, acc.x); acc.y = fmaf(n0, a.y, acc.y);
        acc.z = fmaf(n0, b.x, acc.z); acc.w = fmaf(n0, b.y, acc.w);
        a = h2f2(u1.x); b = h2f2(u1.y);
        acc.x = fmaf(n1, a.x, acc.x); acc.y = fmaf(n1, a.y, acc.y);
        acc.z = fmaf(n1, b.x, acc.z); acc.w = fmaf(n1, b.y, acc.w);
        a = h2f2(u2.x); b = h2f2(u2.y);
        acc.x = fmaf(n2, a.x, acc.x); acc.y = fmaf(n2, a.y, acc.y);
        acc.z = fmaf(n2, b.x, acc.z); acc.w = fmaf(n2, b.y, acc.w);
        a = h2f2(u3.x); b = h2f2(u3.y);
        acc.x = fmaf(n3, a.x, acc.x); acc.y = fmaf(n3, a.y, acc.y);
        acc.z = fmaf(n3, b.x, acc.z); acc.w = fmaf(n3, b.y, acc.w);
    }
    for (; j < end; ++j) {
        int   s0 = __ldg(&g_csr_src[j]);
        float n0 = __ldg(&g_csr_nrm[j]);
        uint2 u0 = h[(size_t)s0 * 32 + lane];
        float2 a = h2f2(u0.x), b = h2f2(u0.y);
        acc.x = fmaf(n0, a.x, acc.x); acc.y = fmaf(n0, a.y, acc.y);
        acc.z = fmaf(n0, b.x, acc.z); acc.w = fmaf(n0, b.y, acc.w);
    }

    float di = g_dinv[w];
    float d2 = di * di;
    uint2 us = h[(size_t)w * 32 + lane];
    float2 ha = h2f2(us.x), hb = h2f2(us.y);
    float4 bb = ((const float4*)b1)[lane];
    float rx = fmaxf(fmaf(ha.x, d2, acc.x) + bb.x, 0.f);
    float ry = fmaxf(fmaf(ha.y, d2, acc.y) + bb.y, 0.f);
    float rz = fmaxf(fmaf(hb.x, d2, acc.z) + bb.z, 0.f);
    float rw = fmaxf(fmaf(hb.y, d2, acc.w) + bb.w, 0.f);
    uint2 o;
    o.x = pkh2(rx, ry);
    o.y = pkh2(rz, rw);
    ((uint2*)g_h1bh)[(size_t)w * 32 + lane] = o;
}

// ---------------- gather layer 2 (C=40, fp16): two nodes per warp -------------
__global__ __launch_bounds__(256) void gather40_kernel(const float* __restrict__ b2,
                                                       float* __restrict__ out) {
    int w = (blockIdx.x * blockDim.x + threadIdx.x) >> 5;
    int lane = threadIdx.x & 31;
    int node = w * 2 + (lane >> 4);
    if (node >= NNODES) return;
    int sub = lane & 15;
    bool active = sub < 10;

    int start = g_rowstart[node];
    int end   = g_rowstart[node + 1];

    const uint2* __restrict__ h = (const uint2*)g_h2h;
    float4 acc = make_float4(0.f, 0.f, 0.f, 0.f);

    int j = start;
    for (; j + 1 < end; j += 2) {
        int   s0 = __ldg(&g_csr_src[j]);
        int   s1 = __ldg(&g_csr_src[j + 1]);
        float n0 = __ldg(&g_csr_nrm[j]);
        float n1 = __ldg(&g_csr_nrm[j + 1]);
        if (active) {
            uint2 u0 = h[(size_t)s0 * 10 + sub];
            uint2 u1 = h[(size_t)s1 * 10 + sub];
            float2 a, b;
            a = h2f2(u0.x); b = h2f2(u0.y);
            acc.x = fmaf(n0, a.x, acc.x); acc.y = fmaf(n0, a.y, acc.y);
            acc.z = fmaf(n0, b.x, acc.z); acc.w = fmaf(n0, b.y, acc.w);
            a = h2f2(u1.x); b = h2f2(u1.y);
            acc.x = fmaf(n1, a.x, acc.x); acc.y = fmaf(n1, a.y, acc.y);
            acc.z = fmaf(n1, b.x, acc.z); acc.w = fmaf(n1, b.y, acc.w);
        }
    }
    if (j < end) {
        int   s0 = __ldg(&g_csr_src[j]);
        float n0 = __ldg(&g_csr_nrm[j]);
        if (active) {
            uint2 u0 = h[(size_t)s0 * 10 + sub];
            float2 a = h2f2(u0.x), b = h2f2(u0.y);
            acc.x = fmaf(n0, a.x, acc.x); acc.y = fmaf(n0, a.y, acc.y);
            acc.z = fmaf(n0, b.x, acc.z); acc.w = fmaf(n0, b.y, acc.w);
        }
    }

    if (active) {
        float di = g_dinv[node];
        float d2 = di * di;
        uint2 us = h[(size_t)node * 10 + sub];
        float2 ha = h2f2(us.x), hb = h2f2(us.y);
        float4 bb = ((const float4*)b2)[sub];
        float4 r;
        r.x = fmaf(ha.x, d2, acc.x) + bb.x;
        r.y = fmaf(ha.y, d2, acc.y) + bb.y;
        r.z = fmaf(hb.x, d2, acc.z) + bb.z;
        r.w = fmaf(hb.y, d2, acc.w) + bb.w;
        *(float4*)&out[(size_t)node * 40 + sub * 4] = r;
    }
}

// -----------------------------------------------------------------------------
extern "C" void kernel_launch(void* const* d_in, const int* in_sizes, int n_in,
                              void* d_out, int out_size) {
    const float* x   = (const float*)d_in[0];
    const int*   ei  = (const int*)  d_in[1];
    const float* W1  = (const float*)d_in[2];
    const float* b1  = (const float*)d_in[3];
    const float* W2  = (const float*)d_in[4];
    const float* b2  = (const float*)d_in[5];
    float* out = (float*)d_out;

    static bool s_init = false;
    static cudaStream_t s2;
    static cudaEvent_t evA, evB;
    if (!s_init) {   // host-side setup on first (uncaptured) call only
        cudaFuncSetAttribute(gemm128_f16_kernel,
                             cudaFuncAttributeMaxDynamicSharedMemorySize, GEMM128_SMEM);
        cudaFuncSetAttribute(gemm40_f16_kernel,
                             cudaFuncAttributeMaxDynamicSharedMemorySize, GEMM40_SMEM);
        cudaStreamCreateWithFlags(&s2, cudaStreamNonBlocking);
        cudaEventCreateWithFlags(&evA, cudaEventDisableTiming);
        cudaEventCreateWithFlags(&evB, cudaEventDisableTiming);
        s_init = true;
    }

    uint32_t* h1_p;  cudaGetSymbolAddress((void**)&h1_p,  g_h1h);
    uint32_t* h1b_p; cudaGetSymbolAddress((void**)&h1b_p, g_h1bh);
    uint32_t* h2_p;  cudaGetSymbolAddress((void**)&h2_p,  g_h2h);

    // ---- fork: CSR build on s2, concurrent with gemm128 on main stream ----
    cudaEventRecord(evA, 0);
    cudaStreamWaitEvent(s2, evA, 0);
    degree_kernel<<<(NEDGES / 4 + 255) / 256, 256, 0, s2>>>(ei);
    scan_fused_kernel<<<NB, 256, 0, s2>>>();
    csrfill_kernel<<<(NEDGES + 255) / 256, 256, 0, s2>>>(ei);
    cudaEventRecord(evB, s2);

    gemm128_f16_kernel<<<(NNODES + 127) / 128, 256, GEMM128_SMEM>>>(x, W1, h1_p, NNODES);

    // ---- join, then the dependent chain ----
    cudaStreamWaitEvent(0, evB, 0);
    gather128_kernel<<<(NNODES * 32 + 255) / 256, 256>>>(b1);
    gemm40_f16_kernel<<<(NNODES + 127) / 128, 256, GEMM40_SMEM>>>(h1b_p, W2, h2_p, NNODES);
    gather40_kernel<<<((NNODES + 1) / 2 * 32 + 255) / 256, 256>>>(b2, out);
}